// round 1
// baseline (speedup 1.0000x reference)
#include <cuda_runtime.h>

#define NIN 7
#define H   32
#define TPB 128   // threads per block
#define SPT 2     // samples per thread

typedef unsigned long long u64;

// ---- f32x2 packed helpers (sm_100+ PTX) ----
__device__ __forceinline__ u64 pk2(float a, float b) {
    u64 r; asm("mov.b64 %0, {%1, %2};" : "=l"(r) : "f"(a), "f"(b)); return r;
}
__device__ __forceinline__ float2 upk2(u64 v) {
    float2 f; asm("mov.b64 {%0, %1}, %2;" : "=f"(f.x), "=f"(f.y) : "l"(v)); return f;
}
__device__ __forceinline__ u64 ffma2(u64 a, u64 b, u64 c) {
    u64 r; asm("fma.rn.f32x2 %0, %1, %2, %3;" : "=l"(r) : "l"(a), "l"(b), "l"(c)); return r;
}

// tanh(x) = 1 - 2/(exp(2x)+1); MUFU.EX2 + MUFU.RCP, rel err ~1e-6.
// Saturates correctly at +/-1 for large |x| (exp->inf/0).
__device__ __forceinline__ float tanh_fast(float x) {
    float e = __expf(2.0f * x);
    return 1.0f - __fdividef(2.0f, e + 1.0f);
}

__global__ __launch_bounds__(TPB)
void WarpTileMLP_kernel(const float* __restrict__ q,
                        const float* __restrict__ w0, const float* __restrict__ b0,
                        const float* __restrict__ w1, const float* __restrict__ b1,
                        const float* __restrict__ w2, const float* __restrict__ b2,
                        float* __restrict__ out)
{
    // Weights transposed to [i][h] so adjacent h are adjacent in memory:
    // a 64-bit shared load yields an f32x2 weight pair directly.
    __shared__ __align__(16) float sw0[NIN * H];   // sw0[i*32 + h] = w0[h][i]
    __shared__ __align__(16) float sw1[H * H];     // sw1[i*32 + h] = w1[h][i]
    __shared__ __align__(16) float sb0[H];
    __shared__ __align__(16) float sb1[H];
    __shared__ __align__(16) float sw2[H];
    __shared__ float sb2s;

    const int tid = threadIdx.x;
    for (int k = tid; k < NIN * H; k += TPB) {
        int i = k >> 5, h = k & 31;
        sw0[k] = w0[h * NIN + i];
    }
    for (int k = tid; k < H * H; k += TPB) {
        int i = k >> 5, h = k & 31;
        sw1[k] = w1[h * H + i];
    }
    if (tid < H) { sb0[tid] = b0[tid]; sb1[tid] = b1[tid]; sw2[tid] = w2[tid]; }
    if (tid == 0) sb2s = b2[0];
    __syncthreads();

    const long t = (long)blockIdx.x * TPB + tid;

    // Load 2 samples = 14 contiguous floats = 7 aligned float2 loads.
    const float2* qv = (const float2*)q;
    float v[14];
#pragma unroll
    for (int j = 0; j < 7; ++j) {
        float2 p = __ldg(&qv[t * 7 + j]);
        v[2 * j] = p.x; v[2 * j + 1] = p.y;
    }
    // sample A = v[0..6], sample B = v[7..13]

    const ulonglong2* sw0v = (const ulonglong2*)sw0;  // [i*8 + c] : 2 h-pairs
    const ulonglong2* sw1v = (const ulonglong2*)sw1;
    const u64* sb0p = (const u64*)sb0;
    const u64* sb1p = (const u64*)sb1;
    const u64* sw2p = (const u64*)sw2;

    u64 accA[16], accB[16];

    // ---------------- Layer 0: 7 -> 32 ----------------
#pragma unroll
    for (int p = 0; p < 16; ++p) { u64 bb = sb0p[p]; accA[p] = bb; accB[p] = bb; }
#pragma unroll
    for (int i = 0; i < NIN; ++i) {
        u64 xa = pk2(v[i], v[i]);
        u64 xb = pk2(v[7 + i], v[7 + i]);
#pragma unroll
        for (int c = 0; c < 8; ++c) {
            ulonglong2 w = sw0v[i * 8 + c];
            accA[2 * c]     = ffma2(w.x, xa, accA[2 * c]);
            accA[2 * c + 1] = ffma2(w.y, xa, accA[2 * c + 1]);
            accB[2 * c]     = ffma2(w.x, xb, accB[2 * c]);
            accB[2 * c + 1] = ffma2(w.y, xb, accB[2 * c + 1]);
        }
    }

    float zA[H], zB[H];
#pragma unroll
    for (int p = 0; p < 16; ++p) {
        float2 a = upk2(accA[p]);
        zA[2 * p] = tanh_fast(a.x); zA[2 * p + 1] = tanh_fast(a.y);
        float2 b = upk2(accB[p]);
        zB[2 * p] = tanh_fast(b.x); zB[2 * p + 1] = tanh_fast(b.y);
    }

    // ---------------- Layer 1: 32 -> 32 ----------------
#pragma unroll
    for (int p = 0; p < 16; ++p) { u64 bb = sb1p[p]; accA[p] = bb; accB[p] = bb; }
#pragma unroll
    for (int i = 0; i < H; ++i) {
        u64 xa = pk2(zA[i], zA[i]);
        u64 xb = pk2(zB[i], zB[i]);
#pragma unroll
        for (int c = 0; c < 8; ++c) {
            ulonglong2 w = sw1v[i * 8 + c];
            accA[2 * c]     = ffma2(w.x, xa, accA[2 * c]);
            accA[2 * c + 1] = ffma2(w.y, xa, accA[2 * c + 1]);
            accB[2 * c]     = ffma2(w.x, xb, accB[2 * c]);
            accB[2 * c + 1] = ffma2(w.y, xb, accB[2 * c + 1]);
        }
    }

    // ---------------- tanh + Layer 2: 32 -> 1 ----------------
    u64 oA = pk2(0.0f, 0.0f);
    u64 oB = pk2(0.0f, 0.0f);
#pragma unroll
    for (int p = 0; p < 16; ++p) {
        u64 wp = sw2p[p];
        float2 a = upk2(accA[p]);
        u64 za = pk2(tanh_fast(a.x), tanh_fast(a.y));
        oA = ffma2(wp, za, oA);
        float2 b = upk2(accB[p]);
        u64 zb = pk2(tanh_fast(b.x), tanh_fast(b.y));
        oB = ffma2(wp, zb, oB);
    }

    float2 ra = upk2(oA);
    float2 rb = upk2(oB);
    float bias2 = sb2s;
    float outA = ra.x + ra.y + bias2;
    float outB = rb.x + rb.y + bias2;

    ((float2*)out)[t] = make_float2(outA, outB);
}

extern "C" void kernel_launch(void* const* d_in, const int* in_sizes, int n_in,
                              void* d_out, int out_size)
{
    const float* q  = (const float*)d_in[0];
    const float* w0 = (const float*)d_in[1];
    const float* b0 = (const float*)d_in[2];
    const float* w1 = (const float*)d_in[3];
    const float* b1 = (const float*)d_in[4];
    const float* w2 = (const float*)d_in[5];
    const float* b2 = (const float*)d_in[6];
    float* out = (float*)d_out;

    const int B = in_sizes[0] / NIN;              // 2097152
    const int blocks = B / (TPB * SPT);           // 8192

    WarpTileMLP_kernel<<<blocks, TPB>>>(q, w0, b0, w1, b1, w2, b2, out);
}

// round 2
// speedup vs baseline: 1.1381x; 1.1381x over previous
#include <cuda_runtime.h>

#define NIN 7
#define H   32
#define TPB 128   // threads per block
#define SPT 2     // samples per thread

typedef unsigned long long u64;

// ---- f32x2 packed helpers (sm_100+ PTX) ----
__device__ __forceinline__ u64 pk2(float a, float b) {
    u64 r; asm("mov.b64 %0, {%1, %2};" : "=l"(r) : "f"(a), "f"(b)); return r;
}
__device__ __forceinline__ float2 upk2(u64 v) {
    float2 f; asm("mov.b64 {%0, %1}, %2;" : "=f"(f.x), "=f"(f.y) : "l"(v)); return f;
}
__device__ __forceinline__ u64 ffma2(u64 a, u64 b, u64 c) {
    u64 r; asm("fma.rn.f32x2 %0, %1, %2, %3;" : "=l"(r) : "l"(a), "l"(b), "l"(c)); return r;
}

// tanh(x) = 1 - 2/(exp(2x)+1); MUFU.EX2 + MUFU.RCP, rel err ~1e-6.
__device__ __forceinline__ float tanh_fast(float x) {
    float e = __expf(2.0f * x);
    return 1.0f - __fdividef(2.0f, e + 1.0f);
}

__global__ __launch_bounds__(TPB, 3)
void WarpTileMLP_kernel(const float* __restrict__ q,
                        const float* __restrict__ w0, const float* __restrict__ b0,
                        const float* __restrict__ w1, const float* __restrict__ b1,
                        const float* __restrict__ w2, const float* __restrict__ b2,
                        float* __restrict__ out)
{
    // Weights transposed to [i][h]: adjacent h are adjacent in memory, so a
    // 128-bit shared load (broadcast, conflict-free) yields 2 f32x2 weight pairs.
    __shared__ __align__(16) float sw0[NIN * H];   // sw0[i*32 + h] = w0[h][i]
    __shared__ __align__(16) float sw1[H * H];     // sw1[i*32 + h] = w1[h][i]
    __shared__ __align__(16) float sb0[H];
    __shared__ __align__(16) float sb1[H];
    __shared__ __align__(16) float sw2[H];
    __shared__ float sb2s;

    const int tid = threadIdx.x;
    for (int k = tid; k < NIN * H; k += TPB) {
        int i = k >> 5, h = k & 31;
        sw0[k] = w0[h * NIN + i];
    }
    for (int k = tid; k < H * H; k += TPB) {
        int i = k >> 5, h = k & 31;
        sw1[k] = w1[h * H + i];
    }
    if (tid < H) { sb0[tid] = b0[tid]; sb1[tid] = b1[tid]; sw2[tid] = w2[tid]; }
    if (tid == 0) sb2s = b2[0];
    __syncthreads();

    const long t = (long)blockIdx.x * TPB + tid;

    // Load 2 samples = 14 contiguous floats = 7 aligned float2 loads.
    const float2* qv = (const float2*)q;
    float v[14];
#pragma unroll
    for (int j = 0; j < 7; ++j) {
        float2 p = __ldg(&qv[t * 7 + j]);
        v[2 * j] = p.x; v[2 * j + 1] = p.y;
    }
    // sample A = v[0..6], sample B = v[7..13]

    const ulonglong2* sw0v = (const ulonglong2*)sw0;  // [i*8 + c] : 2 h-pairs
    const ulonglong2* sw1v = (const ulonglong2*)sw1;
    const u64* sb0p = (const u64*)sb0;
    const u64* sb1p = (const u64*)sb1;
    const u64* sw2p = (const u64*)sw2;

    // ---------------- Layer 0: 7 -> 32 ----------------
    u64 accA[16], accB[16];
#pragma unroll
    for (int p = 0; p < 16; ++p) { u64 bb = sb0p[p]; accA[p] = bb; accB[p] = bb; }
#pragma unroll
    for (int i = 0; i < NIN; ++i) {
        u64 xa = pk2(v[i], v[i]);
        u64 xb = pk2(v[7 + i], v[7 + i]);
#pragma unroll
        for (int c = 0; c < 8; ++c) {
            ulonglong2 w = sw0v[i * 8 + c];
            accA[2 * c]     = ffma2(w.x, xa, accA[2 * c]);
            accA[2 * c + 1] = ffma2(w.y, xa, accA[2 * c + 1]);
            accB[2 * c]     = ffma2(w.x, xb, accB[2 * c]);
            accB[2 * c + 1] = ffma2(w.y, xb, accB[2 * c + 1]);
        }
    }

    // tanh -> z (layer-0 acc registers die here)
    float zA[H], zB[H];
#pragma unroll
    for (int p = 0; p < 16; ++p) {
        float2 a = upk2(accA[p]);
        zA[2 * p] = tanh_fast(a.x); zA[2 * p + 1] = tanh_fast(a.y);
        float2 b = upk2(accB[p]);
        zB[2 * p] = tanh_fast(b.x); zB[2 * p + 1] = tanh_fast(b.y);
    }

    // ---------------- Layer 1 + Layer 2, in two halves of 16 hidden units ----
    // Half-accumulators (8 u64 per sample) die into the layer-2 dot product at
    // the end of each half, keeping peak live registers ~120.
    u64 oA = pk2(0.0f, 0.0f);
    u64 oB = pk2(0.0f, 0.0f);

#pragma unroll
    for (int half = 0; half < 2; ++half) {
        u64 a1A[8], a1B[8];
#pragma unroll
        for (int p = 0; p < 8; ++p) {
            u64 bb = sb1p[half * 8 + p];
            a1A[p] = bb; a1B[p] = bb;
        }
#pragma unroll
        for (int i = 0; i < H; ++i) {
            u64 xa = pk2(zA[i], zA[i]);
            u64 xb = pk2(zB[i], zB[i]);
#pragma unroll
            for (int c = 0; c < 4; ++c) {
                ulonglong2 w = sw1v[i * 8 + half * 4 + c];
                a1A[2 * c]     = ffma2(w.x, xa, a1A[2 * c]);
                a1A[2 * c + 1] = ffma2(w.y, xa, a1A[2 * c + 1]);
                a1B[2 * c]     = ffma2(w.x, xb, a1B[2 * c]);
                a1B[2 * c + 1] = ffma2(w.y, xb, a1B[2 * c + 1]);
            }
        }
        // tanh + layer-2 partial reduction for this half
#pragma unroll
        for (int p = 0; p < 8; ++p) {
            u64 wp = sw2p[half * 8 + p];
            float2 a = upk2(a1A[p]);
            u64 za = pk2(tanh_fast(a.x), tanh_fast(a.y));
            oA = ffma2(wp, za, oA);
            float2 b = upk2(a1B[p]);
            u64 zb = pk2(tanh_fast(b.x), tanh_fast(b.y));
            oB = ffma2(wp, zb, oB);
        }
    }

    float2 ra = upk2(oA);
    float2 rb = upk2(oB);
    float bias2 = sb2s;
    float outA = ra.x + ra.y + bias2;
    float outB = rb.x + rb.y + bias2;

    ((float2*)out)[t] = make_float2(outA, outB);
}

extern "C" void kernel_launch(void* const* d_in, const int* in_sizes, int n_in,
                              void* d_out, int out_size)
{
    const float* q  = (const float*)d_in[0];
    const float* w0 = (const float*)d_in[1];
    const float* b0 = (const float*)d_in[2];
    const float* w1 = (const float*)d_in[3];
    const float* b1 = (const float*)d_in[4];
    const float* w2 = (const float*)d_in[5];
    const float* b2 = (const float*)d_in[6];
    float* out = (float*)d_out;

    const int B = in_sizes[0] / NIN;              // 2097152
    const int blocks = B / (TPB * SPT);           // 8192

    WarpTileMLP_kernel<<<blocks, TPB>>>(q, w0, b0, w1, b1, w2, b2, out);
}